// round 17
// baseline (speedup 1.0000x reference)
#include <cuda_runtime.h>
#include <cuda_fp16.h>

#define NN 10000
#define EE 640000
#define FIN 128
#define NH 8
#define FOUT 16
#define NEG 0.2f
#define EPSF 1e-16f

#define GEMM_BLOCKS 625          // 10000 / 16
#define COUNT_BLOCKS ((EE + 127) / 128)

typedef unsigned long long ull;

__device__ __forceinline__ ull ffma2(ull a, ull b, ull c) {
    ull d;
    asm("fma.rn.f32x2 %0, %1, %2, %3;" : "=l"(d) : "l"(a), "l"(b), "l"(c));
    return d;
}
__device__ __forceinline__ float2 unpack2(ull v) {
    float2 r;
    asm("mov.b64 {%0, %1}, %2;" : "=f"(r.x), "=f"(r.y) : "l"(v));
    return r;
}

// ---------------- scratch (static device memory; zero-initialized at load) -----
__device__ __half g_proj16[NN * FIN];   // 2.56 MB, fp16 proj for aggregation
__device__ float g_ssrc[NN * NH];
__device__ float g_stgt[NN * NH];
__device__ int   g_count[NN];           // zeroed at end of k_agg
__device__ int   g_offs[NN + 1];
__device__ int   g_cursor[NN];
__device__ int   g_ssorted[EE];         // src id per CSR slot
__device__ unsigned g_maxsrc[NH];       // zeroed at end of k_agg
__device__ unsigned g_maxtgt[NH];
__device__ float g_C[NH];               // softmax shift constants

__device__ __forceinline__ unsigned f2u_ord(float f) {
    unsigned u = __float_as_uint(f);
    return (u & 0x80000000u) ? ~u : (u | 0x80000000u);
}
__device__ __forceinline__ float u2f_ord(unsigned u) {
    return __uint_as_float((u & 0x80000000u) ? (u ^ 0x80000000u) : ~u);
}

// ---------------- fused: proj+skip GEMM (+bias,+scores)  ||  edge counting -----
// GEMM blocks: 128 threads, 16 nodes; thread t owns output col t of BOTH mats.
// W staged in fp32 smem (k-split 4 x 32 cols, pad-36 rows: 36t mod 32 = 4t ->
// LDS.128 conflict-free). Mainloop uses packed fma.rn.f32x2: 2 MACs/instr.
__global__ void __launch_bounds__(128) k_fused(
    const float* __restrict__ x, const float* __restrict__ Wp,
    const float* __restrict__ Ws, const float* __restrict__ bias,
    const float* __restrict__ sw_src, const float* __restrict__ sw_tgt,
    const int* __restrict__ edges, float* __restrict__ out)
{
    __shared__ float4 xs4[16][32];          // 8 KB
    __shared__ float  wsm[2][128][36];      // 36 KB
    int t = threadIdx.x;

    if (blockIdx.x >= GEMM_BLOCKS) {
        int e = (blockIdx.x - GEMM_BLOCKS) * 128 + t;
        if (e < EE) atomicAdd(&g_count[edges[EE + e]], 1);
        return;
    }

    int node0 = blockIdx.x * 16;

    const float4* xg = (const float4*)(x + node0 * FIN);
    for (int i = t; i < 512; i += 128) xs4[i >> 5][i & 31] = xg[i];

    ull accP2[16], accS2[16];
#pragma unroll
    for (int n = 0; n < 16; n++) { accP2[n] = 0ULL; accS2[n] = 0ULL; }

    for (int ks = 0; ks < 4; ks++) {        // k-split: 32 floats per round
        __syncthreads();                    // also orders x-tile on first pass
        for (int j = t; j < 1024; j += 128) {
            int col = j >> 3, q = j & 7;
            float4 wv = *(const float4*)(Wp + col * FIN + ks * 32 + q * 4);
            float4 sv = *(const float4*)(Ws + col * FIN + ks * 32 + q * 4);
            *(float4*)&wsm[0][col][q * 4] = wv;
            *(float4*)&wsm[1][col][q * 4] = sv;
        }
        __syncthreads();

#pragma unroll
        for (int k4 = 0; k4 < 8; k4++) {
            ulonglong2 wa = *(const ulonglong2*)&wsm[0][t][k4 * 4];
            ulonglong2 wb = *(const ulonglong2*)&wsm[1][t][k4 * 4];
#pragma unroll
            for (int n = 0; n < 16; n++) {
                ulonglong2 xv = *(const ulonglong2*)&xs4[n][ks * 8 + k4];
                accP2[n] = ffma2(wa.x, xv.x, accP2[n]);
                accP2[n] = ffma2(wa.y, xv.y, accP2[n]);
                accS2[n] = ffma2(wb.x, xv.x, accS2[n]);
                accS2[n] = ffma2(wb.y, xv.y, accS2[n]);
            }
        }
    }

    float accP[16];
    float bv = bias[t];
#pragma unroll
    for (int n = 0; n < 16; n++) {
        float2 up = unpack2(accP2[n]);
        float2 us = unpack2(accS2[n]);
        accP[n] = up.x + up.y;
        g_proj16[(node0 + n) * FIN + t] = __float2half(accP[n]);
        out[(node0 + n) * FIN + t] = us.x + us.y + bv;   // skip + bias baseline
    }

    // ---- epilogue: per-(node,head) scores via 16-lane shuffle reduction ----
    float swv = sw_src[t], twv = sw_tgt[t];
    int h = t >> 4;
    bool leader = (t & 15) == 0;
    float msrc = -3.4e38f, mtgt = -3.4e38f;
#pragma unroll
    for (int n = 0; n < 16; n++) {
        float ps = accP[n] * swv;
        float pt = accP[n] * twv;
#pragma unroll
        for (int o = 8; o; o >>= 1) {
            ps += __shfl_down_sync(0xffffffffu, ps, o, 16);
            pt += __shfl_down_sync(0xffffffffu, pt, o, 16);
        }
        if (leader) {
            g_ssrc[(node0 + n) * NH + h] = ps;
            g_stgt[(node0 + n) * NH + h] = pt;
            msrc = fmaxf(msrc, ps);
            mtgt = fmaxf(mtgt, pt);
        }
    }
    if (leader) {
        atomicMax(&g_maxsrc[h], f2u_ord(msrc));
        atomicMax(&g_maxtgt[h], f2u_ord(mtgt));
    }
}

// ---------------- CSR scan: coalesced smem staging + warp-shuffle scan ---------
__global__ void __launch_bounds__(1024) k_scan() {
    const int PER = 10;                 // 1024 * 10 >= NN
    __shared__ int cs[NN];              // 40 KB, coalesced staging
    __shared__ int wt[32];
    int t = threadIdx.x;

    for (int i = t; i < NN; i += 1024) cs[i] = g_count[i];
    __syncthreads();

    int base = t * PER;
    int loc[PER];
    int sum = 0;
#pragma unroll
    for (int i = 0; i < PER; i++) {
        int idx = base + i;
        int v = (idx < NN) ? cs[idx] : 0;
        loc[i] = sum;
        sum += v;
    }
    int lane = t & 31, w = t >> 5;
    int s = sum;
#pragma unroll
    for (int o = 1; o < 32; o <<= 1) {
        int y = __shfl_up_sync(0xffffffffu, s, o);
        if (lane >= o) s += y;
    }
    if (lane == 31) wt[w] = s;
    __syncthreads();
    if (w == 0) {
        int v = wt[lane];
        int s2 = v;
#pragma unroll
        for (int o = 1; o < 32; o <<= 1) {
            int y = __shfl_up_sync(0xffffffffu, s2, o);
            if (lane >= o) s2 += y;
        }
        wt[lane] = s2 - v;
    }
    __syncthreads();
    int off = (s - sum) + wt[w];
#pragma unroll
    for (int i = 0; i < PER; i++) {
        int idx = base + i;
        if (idx < NN) cs[idx] = off + loc[i];
    }
    __syncthreads();
    for (int i = t; i < NN; i += 1024) {
        int o = cs[i];
        g_offs[i] = o;
        g_cursor[i] = o;
    }
    if (t == 1023) g_offs[NN] = off + sum;

    if (t < NH) {
        float c = u2f_ord(g_maxsrc[t]) + u2f_ord(g_maxtgt[t]);
        g_C[t] = fmaxf(c, NEG * c);
    }
}

// ---------------- CSR scatter: src ids into segment order ----------------
__global__ void k_scatter(const int* __restrict__ edges) {
    int e = blockIdx.x * 256 + threadIdx.x;
    if (e < EE) {
        int p = atomicAdd(&g_cursor[edges[EE + e]], 1);
        g_ssorted[p] = edges[e];
    }
}

// ---------------- aggregation: paired-edge LDG.128, zero-padded tiles ----------
// Tile = 64 edges. Staging writes exp (0 for pad slots) + premultiplied row
// offsets. Compute: lane l handles edge 2p+(l>>4), features [8(l&15), +8):
// ONE LDG.128 covers 2 proj rows per warp instruction -> LDG/IMAD/LDS halved.
__global__ void __launch_bounds__(128) k_agg(float* __restrict__ out) {
    __shared__ float  att_s[64][NH];
    __shared__ int    off_s[64];
    __shared__ float  red_s[4][32][8];
    __shared__ float  den_red[128];
    __shared__ float  stgt_s[NH], C_s[NH];

    int n = blockIdx.x, t = threadIdx.x;
    int lane = t & 31, w = t >> 5;
    int hs = t & 7;                              // staging head
    int g = lane & 15;                           // feature group (8 halves)
    int hf = g >> 1;                             // compute head
    int epar = lane >> 4;                        // which edge of the pair

    if (t < NH) { stgt_s[t] = g_stgt[n * NH + t]; C_s[t] = g_C[t]; }
    if (t == 8) g_count[n] = 0;                  // re-zero for next replay
    if (n == 0 && t >= 16 && t < 24) g_maxsrc[t - 16] = 0u;
    if (n == 0 && t >= 24 && t < 32) g_maxtgt[t - 24] = 0u;
    __syncthreads();

    int start = g_offs[n], end = g_offs[n + 1];
    float stgt_h = stgt_s[hs];
    float C_h = C_s[hs];
    float acc[8];
#pragma unroll
    for (int i = 0; i < 8; i++) acc[i] = 0.f;
    float den_part = 0.f;

    for (int base = start; base < end; base += 64) {
        int m = min(64, end - base);
        __syncthreads();
#pragma unroll
        for (int r = 0; r < 4; r++) {            // stage 64 slots x 8 heads
            int slot = (t >> 3) + 16 * r;
            int sid = 0;
            float ex = 0.f;
            if (slot < m) {
                sid = g_ssorted[base + slot];
                float v = g_ssrc[sid * NH + hs] + stgt_h;
                ex = __expf(fmaxf(v, NEG * v) - C_h);
            }
            att_s[slot][hs] = ex;                // pad -> 0
            den_part += ex;
            if (hs == 0) off_s[slot] = sid * FIN;   // pad -> row 0, weight 0
        }
        __syncthreads();

        int np = (m + 1) >> 1;                   // pairs (odd tail zero-padded)
        int p = w;
        for (; p + 4 < np; p += 8) {             // 2 pairs/iter -> 4 edges, MLP=2x
            int e0 = 2 * p + epar;
            int e1 = 2 * (p + 4) + epar;
            float a0 = att_s[e0][hf];
            float a1 = att_s[e1][hf];
            int4 q0 = *((const int4*)(g_proj16 + off_s[e0]) + g);
            int4 q1 = *((const int4*)(g_proj16 + off_s[e1]) + g);
            float2 f0 = __half22float2(*(__half2*)&q0.x);
            float2 f1 = __half22float2(*(__half2*)&q0.y);
            float2 f2 = __half22float2(*(__half2*)&q0.z);
            float2 f3 = __half22float2(*(__half2*)&q0.w);
            acc[0] += a0 * f0.x; acc[1] += a0 * f0.y;
            acc[2] += a0 * f1.x; acc[3] += a0 * f1.y;
            acc[4] += a0 * f2.x; acc[5] += a0 * f2.y;
            acc[6] += a0 * f3.x; acc[7] += a0 * f3.y;
            f0 = __half22float2(*(__half2*)&q1.x);
            f1 = __half22float2(*(__half2*)&q1.y);
            f2 = __half22float2(*(__half2*)&q1.z);
            f3 = __half22float2(*(__half2*)&q1.w);
            acc[0] += a1 * f0.x; acc[1] += a1 * f0.y;
            acc[2] += a1 * f1.x; acc[3] += a1 * f1.y;
            acc[4] += a1 * f2.x; acc[5] += a1 * f2.y;
            acc[6] += a1 * f3.x; acc[7] += a1 * f3.y;
        }
        for (; p < np; p += 4) {
            int e0 = 2 * p + epar;
            float a0 = att_s[e0][hf];
            int4 q0 = *((const int4*)(g_proj16 + off_s[e0]) + g);
            float2 f0 = __half22float2(*(__half2*)&q0.x);
            float2 f1 = __half22float2(*(__half2*)&q0.y);
            float2 f2 = __half22float2(*(__half2*)&q0.z);
            float2 f3 = __half22float2(*(__half2*)&q0.w);
            acc[0] += a0 * f0.x; acc[1] += a0 * f0.y;
            acc[2] += a0 * f1.x; acc[3] += a0 * f1.y;
            acc[4] += a0 * f2.x; acc[5] += a0 * f2.y;
            acc[6] += a0 * f3.x; acc[7] += a0 * f3.y;
        }
    }

#pragma unroll
    for (int i = 0; i < 8; i++) red_s[w][lane][i] = acc[i];
    den_red[t] = den_part;
    __syncthreads();
    if (w == 0 && lane < 16) {
        float s[8];
#pragma unroll
        for (int i = 0; i < 8; i++) s[i] = 0.f;
#pragma unroll
        for (int ww = 0; ww < 4; ww++)
#pragma unroll
            for (int par = 0; par < 2; par++)
#pragma unroll
                for (int i = 0; i < 8; i++)
                    s[i] += red_s[ww][lane + 16 * par][i];
        int hh = lane >> 1;
        float den = 0.f;
#pragma unroll
        for (int k = 0; k < 16; k++) den += den_red[hh + k * 8];
        float inv = 1.0f / (den + EPSF);
        float4* o4 = (float4*)(out + n * FIN + lane * 8);
        float4 oa = o4[0], ob = o4[1];
        oa.x += s[0] * inv; oa.y += s[1] * inv; oa.z += s[2] * inv; oa.w += s[3] * inv;
        ob.x += s[4] * inv; ob.y += s[5] * inv; ob.z += s[6] * inv; ob.w += s[7] * inv;
        o4[0] = oa; o4[1] = ob;
    }
}

// ---------------- launch ----------------
extern "C" void kernel_launch(void* const* d_in, const int* in_sizes, int n_in,
                              void* d_out, int out_size)
{
    const float* x     = (const float*)d_in[0];
    const int*   edges = (const int*)d_in[1];     // int32 (JAX x64 disabled)
    const float* Wp    = (const float*)d_in[2];
    const float* Ws    = (const float*)d_in[3];
    const float* s_src = (const float*)d_in[4];
    const float* s_tgt = (const float*)d_in[5];
    const float* bias  = (const float*)d_in[6];
    float* out = (float*)d_out;

    k_fused<<<GEMM_BLOCKS + COUNT_BLOCKS, 128>>>(x, Wp, Ws, bias, s_src, s_tgt, edges, out);
    k_scan<<<1, 1024>>>();
    k_scatter<<<(EE + 255) / 256, 256>>>(edges);
    k_agg<<<NN, 128>>>(out);
}